// round 1
// baseline (speedup 1.0000x reference)
#include <cuda_runtime.h>
#include <cstdint>

// CausalMemoryAttention: B=16, S=4096, D=1024
//
// Math restructure (exact):
//   Q  = query @ Wq^T + bq                         [16,1024]
//   qt = Q @ Wk          (so Q.K[b,s] = mb[b,s].qt[b] + Q[b].bk)
//   score[b,s] = (mb[b,s].qt[b] + qbk[b]) / 32 * exp(-0.01*(ct[b]-ts[b,s]))
//   p = exp(score)  (no max subtraction needed; |score| ~ O(5))
//   attn = p / sum(p)
//   m[b] = (sum_s p_s * mb[b,s]) / sum(p)
//   attended = m @ Wv^T + bv   (bias exact since sum(attn)=1)
//
// Memory_bank (268 MB) is read exactly ONCE, in the fused k_main kernel.

#define B 16
#define S 4096
#define D 1024
#define D4 256          // D / 4 (float4 count per row)
#define ROWS_PER_WARP 16
#define WARPS_MAIN 8
#define CTAS_PER_B (S / (WARPS_MAIN * ROWS_PER_WARP))   // 32
#define NCTA_MAIN (B * CTAS_PER_B)                      // 512
#define QT_SPLITS 16    // d-splits for the qt GEMM

// -------- scratch (device globals; no dynamic allocation allowed) --------
__device__ __align__(16) float g_Q[B * D];
__device__ __align__(16) float g_qt[B * D];
__device__ __align__(16) float g_qt_part[QT_SPLITS * B * D];
__device__ float g_qbk[B];
__device__ __align__(16) float g_p[B * S];
__device__ __align__(16) float g_macc[NCTA_MAIN * D];   // per-CTA partial weighted sums
__device__ float g_Epart[NCTA_MAIN];
__device__ __align__(16) float g_m[B * D];

// ============================================================
// k_gemm_nt: Out[b,d] = sum_e X[b,e] * W[d,e] + bias[d]
// mode 0: X = Xext (query),  Out = g_Q
// mode 1: X = g_m,           Out = OutExt (attended region of d_out)
// One warp per output column d; 2-way batch ILP. Grid 128 x 256 threads.
// ============================================================
__global__ __launch_bounds__(256) void k_gemm_nt(
    const float* __restrict__ Xext, const float* __restrict__ W,
    const float* __restrict__ bias, float* __restrict__ OutExt, int mode)
{
    int warp = threadIdx.x >> 5, lane = threadIdx.x & 31;
    int d = blockIdx.x * 8 + warp;

    const float* Xp = (mode == 0) ? Xext : g_m;
    float* Outp = (mode == 0) ? g_Q : OutExt;

    const float4* W4 = reinterpret_cast<const float4*>(W) + (size_t)d * D4;
    const float4* X4 = reinterpret_cast<const float4*>(Xp);

    float4 w[8];
#pragma unroll
    for (int k = 0; k < 8; k++) w[k] = W4[k * 32 + lane];
    float bb = bias[d];

#pragma unroll
    for (int b = 0; b < B; b += 2) {
        float sa = 0.f, sb = 0.f;
#pragma unroll
        for (int k = 0; k < 8; k++) {
            float4 xa = X4[b * D4 + k * 32 + lane];
            float4 xb = X4[(b + 1) * D4 + k * 32 + lane];
            sa += xa.x * w[k].x; sa += xa.y * w[k].y;
            sa += xa.z * w[k].z; sa += xa.w * w[k].w;
            sb += xb.x * w[k].x; sb += xb.y * w[k].y;
            sb += xb.z * w[k].z; sb += xb.w * w[k].w;
        }
#pragma unroll
        for (int o = 16; o > 0; o >>= 1) {
            sa += __shfl_xor_sync(0xffffffffu, sa, o);
            sb += __shfl_xor_sync(0xffffffffu, sb, o);
        }
        if (lane == 0) {
            Outp[b * D + d] = sa + bb;
            Outp[(b + 1) * D + d] = sb + bb;
        }
    }
}

// ============================================================
// k_qbk: g_qbk[b] = dot(g_Q[b,:], bk).  1 block, 512 threads (warp per b).
// ============================================================
__global__ void k_qbk(const float* __restrict__ bk)
{
    int b = threadIdx.x >> 5, lane = threadIdx.x & 31;
    const float4* Q4 = reinterpret_cast<const float4*>(g_Q) + b * D4;
    const float4* B4 = reinterpret_cast<const float4*>(bk);
    float s = 0.f;
#pragma unroll
    for (int k = 0; k < 8; k++) {
        float4 q = Q4[k * 32 + lane];
        float4 v = B4[k * 32 + lane];
        s += q.x * v.x + q.y * v.y + q.z * v.z + q.w * v.w;
    }
#pragma unroll
    for (int o = 16; o > 0; o >>= 1) s += __shfl_xor_sync(0xffffffffu, s, o);
    if (lane == 0) g_qbk[b] = s;
}

// ============================================================
// k_qt: partial qt[b,e] = sum_{d in split} Q[b,d] * Wk[d,e]   (NN layout)
// grid (8 e-tiles of 128, 16 d-splits of 64), 128 threads.
// ============================================================
__global__ __launch_bounds__(128) void k_qt(const float* __restrict__ Wk)
{
    __shared__ __align__(16) float Qs[64 * 16];   // [d_local][b]
    int e = blockIdx.x * 128 + threadIdx.x;
    int d0 = blockIdx.y * 64;

    for (int i = threadIdx.x; i < 1024; i += 128) {
        int bb = i >> 6, dl = i & 63;
        Qs[dl * 16 + bb] = g_Q[bb * D + d0 + dl];
    }
    __syncthreads();

    float acc[16];
#pragma unroll
    for (int bb = 0; bb < 16; bb++) acc[bb] = 0.f;

    for (int dl = 0; dl < 64; dl++) {
        float w = Wk[(size_t)(d0 + dl) * D + e];
        const float4* q4 = reinterpret_cast<const float4*>(&Qs[dl * 16]);
#pragma unroll
        for (int j = 0; j < 4; j++) {
            float4 q = q4[j];
            acc[4 * j + 0] += q.x * w;
            acc[4 * j + 1] += q.y * w;
            acc[4 * j + 2] += q.z * w;
            acc[4 * j + 3] += q.w * w;
        }
    }
#pragma unroll
    for (int bb = 0; bb < 16; bb++)
        g_qt_part[(blockIdx.y * 16 + bb) * D + e] = acc[bb];
}

// k_qt_reduce: sum the 16 d-split partials.  grid 64 x 256.
__global__ void k_qt_reduce()
{
    int idx = blockIdx.x * 256 + threadIdx.x;      // < 16384 = b*1024+e
    int b = idx >> 10, e = idx & 1023;
    float s = 0.f;
#pragma unroll
    for (int sp = 0; sp < QT_SPLITS; sp++) s += g_qt_part[(sp * 16 + b) * D + e];
    g_qt[idx] = s;
}

// ============================================================
// k_main: the single streaming pass over memory_bank.
// CTA = (b, chunk of 128 rows). Warp handles 16 rows; each row is loaded
// once into registers, used for the dot AND the p-weighted accumulation.
// Emits per-CTA partials: g_macc[cta][1024], g_Epart[cta]; and p -> g_p.
// ============================================================
__global__ __launch_bounds__(256) void k_main(
    const float* __restrict__ mb, const float* __restrict__ ts,
    const float* __restrict__ ct)
{
    __shared__ float4 sacc[WARPS_MAIN][D4];
    __shared__ float sE[WARPS_MAIN];

    int b = blockIdx.x >> 5;          // /CTAS_PER_B
    int c = blockIdx.x & 31;
    int warp = threadIdx.x >> 5, lane = threadIdx.x & 31;

    const float4* qt4 = reinterpret_cast<const float4*>(g_qt) + b * D4;
    float4 q[8];
#pragma unroll
    for (int k = 0; k < 8; k++) q[k] = qt4[k * 32 + lane];
    float qb = g_qbk[b];
    float curt = ct[b];

    float4 acc[8];
#pragma unroll
    for (int k = 0; k < 8; k++) acc[k] = make_float4(0.f, 0.f, 0.f, 0.f);
    float Ew = 0.f;

    int s0 = c * 128 + warp * ROWS_PER_WARP;
    const float4* rowbase = reinterpret_cast<const float4*>(mb) + (size_t)b * S * D4;

#pragma unroll 1
    for (int r = 0; r < ROWS_PER_WARP; r++) {
        int s = s0 + r;
        const float4* row = rowbase + (size_t)s * D4;
        float4 v[8];
#pragma unroll
        for (int k = 0; k < 8; k++) v[k] = row[k * 32 + lane];

        float d0 = 0.f, d1 = 0.f, d2 = 0.f, d3 = 0.f;
#pragma unroll
        for (int k = 0; k < 8; k++) {
            d0 += v[k].x * q[k].x; d1 += v[k].y * q[k].y;
            d2 += v[k].z * q[k].z; d3 += v[k].w * q[k].w;
        }
        float dsum = (d0 + d1) + (d2 + d3);
#pragma unroll
        for (int o = 16; o > 0; o >>= 1) dsum += __shfl_xor_sync(0xffffffffu, dsum, o);

        float tw = __expf(-0.01f * (curt - ts[b * S + s]));
        float p = __expf((dsum + qb) * 0.03125f * tw);
        if (lane == 0) g_p[b * S + s] = p;
        Ew += p;
#pragma unroll
        for (int k = 0; k < 8; k++) {
            acc[k].x += p * v[k].x; acc[k].y += p * v[k].y;
            acc[k].z += p * v[k].z; acc[k].w += p * v[k].w;
        }
    }

#pragma unroll
    for (int k = 0; k < 8; k++) sacc[warp][k * 32 + lane] = acc[k];
    if (lane == 0) sE[warp] = Ew;
    __syncthreads();

    int t = threadIdx.x;
    float4 r0 = sacc[0][t];
#pragma unroll
    for (int w = 1; w < WARPS_MAIN; w++) {
        float4 v = sacc[w][t];
        r0.x += v.x; r0.y += v.y; r0.z += v.z; r0.w += v.w;
    }
    reinterpret_cast<float4*>(g_macc)[(size_t)blockIdx.x * D4 + t] = r0;
    if (t == 0) {
        float e = 0.f;
#pragma unroll
        for (int w = 0; w < WARPS_MAIN; w++) e += sE[w];
        g_Epart[blockIdx.x] = e;
    }
}

// ============================================================
// k_combine: per batch — E = sum parts; attn = p/E; m = (sum macc)/E.
// grid 16 x 256.
// ============================================================
__global__ void k_combine(float* __restrict__ attn)
{
    __shared__ float sInv;
    int b = blockIdx.x, tid = threadIdx.x;

    if (tid < 32) {
        float e = g_Epart[b * CTAS_PER_B + tid];   // exactly 32 parts
#pragma unroll
        for (int o = 16; o > 0; o >>= 1) e += __shfl_xor_sync(0xffffffffu, e, o);
        if (tid == 0) sInv = 1.f / e;
    }
    __syncthreads();
    float inv = sInv;

    for (int s = tid; s < S; s += 256) attn[b * S + s] = g_p[b * S + s] * inv;

    const float4* mp = reinterpret_cast<const float4*>(g_macc);
    float4 a = make_float4(0.f, 0.f, 0.f, 0.f);
#pragma unroll
    for (int c = 0; c < CTAS_PER_B; c++) {
        float4 v = mp[(size_t)(b * CTAS_PER_B + c) * D4 + tid];
        a.x += v.x; a.y += v.y; a.z += v.z; a.w += v.w;
    }
    a.x *= inv; a.y *= inv; a.z *= inv; a.w *= inv;
    reinterpret_cast<float4*>(g_m)[b * D4 + tid] = a;
}

// ============================================================
extern "C" void kernel_launch(void* const* d_in, const int* in_sizes, int n_in,
                              void* d_out, int out_size)
{
    const float* query = (const float*)d_in[0];
    const float* mb    = (const float*)d_in[1];
    const float* ts    = (const float*)d_in[2];
    const float* ct    = (const float*)d_in[3];
    const float* Wq    = (const float*)d_in[4];
    const float* bq    = (const float*)d_in[5];
    const float* Wk    = (const float*)d_in[6];
    const float* bk    = (const float*)d_in[7];
    const float* Wv    = (const float*)d_in[8];
    const float* bv    = (const float*)d_in[9];
    (void)in_sizes; (void)n_in; (void)out_size;

    float* attended = (float*)d_out;            // [16,1024]
    float* attn     = (float*)d_out + B * D;    // [16,4096]

    k_gemm_nt<<<128, 256>>>(query, Wq, bq, nullptr, 0);   // g_Q
    k_qbk<<<1, 512>>>(bk);                                 // g_qbk
    k_qt<<<dim3(8, QT_SPLITS), 128>>>(Wk);                 // qt partials
    k_qt_reduce<<<64, 256>>>();                            // g_qt
    k_main<<<NCTA_MAIN, 256>>>(mb, ts, ct);                // the 268 MB pass
    k_combine<<<B, 256>>>(attn);                           // E, attn, g_m
    k_gemm_nt<<<128, 256>>>(nullptr, Wv, bv, attended, 1); // attended
}

// round 3
// speedup vs baseline: 1.0215x; 1.0215x over previous
#include <cuda_runtime.h>
#include <cstdint>

// CausalMemoryAttention: B=16, S=4096, D=1024
// Exact restructure (validated R1, rel_err 1.3e-6):
//   Q  = query @ Wq^T + bq
//   qt = Q @ Wk ; qbk = Q.bk      (so Q.K[b,s] = mb[b,s].qt[b] + qbk[b])
//   p  = exp(score * temporal_weight)  (no max pass needed; |score| ~ O(5))
//   attn = p / sum p ;  m = (sum p*mb) / sum p ;  attended = m @ Wv^T + bv
// memory_bank (268 MB) is streamed exactly once via a cp.async smem pipeline.

#define B 16
#define S 4096
#define D 1024
#define D4 256
#define QT_SPLITS 16
#define CTAS_PER_B 18
#define NCTA_MAIN (B * CTAS_PER_B)        // 288  (<=296 => single wave at 2 CTA/SM)
#define DEPTH 3
#define STAGE_ROWS 8
#define STAGE_F4 (STAGE_ROWS * D4)        // 2048 float4
#define STAGE_BYTES (STAGE_F4 * 16)       // 32 KB
#define SMEM_MAIN (DEPTH * STAGE_BYTES)   // 96 KB

// -------- scratch (device globals; no dynamic allocation) --------
__device__ __align__(16) float g_Q[B * D];
__device__ __align__(16) float g_qt_part[QT_SPLITS * B * D];
__device__ __align__(16) float g_p[B * S];
__device__ __align__(16) float g_macc[NCTA_MAIN * D];
__device__ float g_Epart[NCTA_MAIN];
__device__ __align__(16) float g_m[B * D];

// ---------------- cp.async helpers ----------------
__device__ __forceinline__ void cp_async16(uint32_t smem, const void* gmem) {
    asm volatile("cp.async.cg.shared.global [%0], [%1], 16;" :: "r"(smem), "l"(gmem));
}
__device__ __forceinline__ void cp_commit() {
    asm volatile("cp.async.commit_group;" ::: "memory");
}
template <int N> __device__ __forceinline__ void cp_wait() {
    asm volatile("cp.async.wait_group %0;" :: "n"(N) : "memory");
}

// ============================================================
// k_gemm_nt: Out[b,d] = sum_e X[b,e] * W[d,e] + bias[d]
// mode 0: X=query -> g_Q ; mode 1: X=g_m -> OutExt (attended)
// ============================================================
__global__ __launch_bounds__(256) void k_gemm_nt(
    const float* __restrict__ Xext, const float* __restrict__ W,
    const float* __restrict__ bias, float* __restrict__ OutExt, int mode)
{
    int warp = threadIdx.x >> 5, lane = threadIdx.x & 31;
    int d = blockIdx.x * 8 + warp;

    const float* Xp = (mode == 0) ? Xext : g_m;
    float* Outp = (mode == 0) ? g_Q : OutExt;

    const float4* W4 = reinterpret_cast<const float4*>(W) + (size_t)d * D4;
    const float4* X4 = reinterpret_cast<const float4*>(Xp);

    float4 w[8];
#pragma unroll
    for (int k = 0; k < 8; k++) w[k] = W4[k * 32 + lane];
    float bb = bias[d];

#pragma unroll
    for (int b = 0; b < B; b += 2) {
        float sa = 0.f, sb = 0.f;
#pragma unroll
        for (int k = 0; k < 8; k++) {
            float4 xa = X4[b * D4 + k * 32 + lane];
            float4 xb = X4[(b + 1) * D4 + k * 32 + lane];
            sa += xa.x * w[k].x; sa += xa.y * w[k].y;
            sa += xa.z * w[k].z; sa += xa.w * w[k].w;
            sb += xb.x * w[k].x; sb += xb.y * w[k].y;
            sb += xb.z * w[k].z; sb += xb.w * w[k].w;
        }
#pragma unroll
        for (int o = 16; o > 0; o >>= 1) {
            sa += __shfl_xor_sync(0xffffffffu, sa, o);
            sb += __shfl_xor_sync(0xffffffffu, sb, o);
        }
        if (lane == 0) {
            Outp[b * D + d] = sa + bb;
            Outp[(b + 1) * D + d] = sb + bb;
        }
    }
}

// ============================================================
// k_qt: partial qt[b,e] = sum_{d in split} Q[b,d] * Wk[d,e]
// grid (8 e-tiles of 128, 16 d-splits of 64), 128 threads.
// ============================================================
__global__ __launch_bounds__(128) void k_qt(const float* __restrict__ Wk)
{
    __shared__ __align__(16) float Qs[64 * 16];
    int e = blockIdx.x * 128 + threadIdx.x;
    int d0 = blockIdx.y * 64;

    for (int i = threadIdx.x; i < 1024; i += 128) {
        int bb = i >> 6, dl = i & 63;
        Qs[dl * 16 + bb] = g_Q[bb * D + d0 + dl];
    }
    __syncthreads();

    float acc[16];
#pragma unroll
    for (int bb = 0; bb < 16; bb++) acc[bb] = 0.f;

#pragma unroll 8
    for (int dl = 0; dl < 64; dl++) {
        float w = Wk[(size_t)(d0 + dl) * D + e];
        const float4* q4 = reinterpret_cast<const float4*>(&Qs[dl * 16]);
#pragma unroll
        for (int j = 0; j < 4; j++) {
            float4 q = q4[j];
            acc[4 * j + 0] += q.x * w;
            acc[4 * j + 1] += q.y * w;
            acc[4 * j + 2] += q.z * w;
            acc[4 * j + 3] += q.w * w;
        }
    }
#pragma unroll
    for (int bb = 0; bb < 16; bb++)
        g_qt_part[(size_t)(blockIdx.y * 16 + bb) * D + e] = acc[bb];
}

// ============================================================
// k_main: single streaming pass over memory_bank via cp.async pipeline.
// CTA = (b, 1/18th of the 512 8-row stages). 8 warps; warp w computes
// row w of each stage from smem. Prologue: while the first DEPTH stages
// stream in, the CTA reduces the 16 qt partials and computes qbk (free).
// ============================================================
__global__ __launch_bounds__(256, 2) void k_main(
    const float* __restrict__ mb, const float* __restrict__ ts,
    const float* __restrict__ ct, const float* __restrict__ bk)
{
    extern __shared__ __align__(16) float4 sbuf[];   // DEPTH * STAGE_F4
    __shared__ float sE[8];

    int b = blockIdx.x / CTAS_PER_B;
    int j = blockIdx.x % CTAS_PER_B;
    int warp = threadIdx.x >> 5, lane = threadIdx.x & 31, tid = threadIdx.x;

    // 512 stages per batch split 8x29 + 10x28
    int nst = (j < 8) ? 29 : 28;
    int st0 = (j < 8) ? j * 29 : 232 + (j - 8) * 28;

    const float* gsrc = mb + (size_t)b * S * D + (size_t)st0 * STAGE_ROWS * D;
    uint32_t sb = (uint32_t)__cvta_generic_to_shared(sbuf);

    // ---- prologue: issue first DEPTH stages ----
    int issued = 0;
    for (; issued < DEPTH && issued < nst; issued++) {
        uint32_t dst = sb + (uint32_t)(issued % DEPTH) * STAGE_BYTES;
        const float* src = gsrc + (size_t)issued * STAGE_ROWS * D;
        for (int c = tid; c < STAGE_F4; c += 256)
            cp_async16(dst + (uint32_t)c * 16, src + (size_t)c * 4);
        cp_commit();
    }

    // ---- qt split-reduce for this b (overlaps DRAM ramp) ----
    float4 q[8];
#pragma unroll
    for (int k = 0; k < 8; k++) q[k] = make_float4(0.f, 0.f, 0.f, 0.f);
    for (int sp = 0; sp < QT_SPLITS; sp++) {
        const float4* qp = reinterpret_cast<const float4*>(g_qt_part)
                           + (size_t)(sp * B + b) * D4;
#pragma unroll
        for (int k = 0; k < 8; k++) {
            float4 v = qp[k * 32 + lane];
            q[k].x += v.x; q[k].y += v.y; q[k].z += v.z; q[k].w += v.w;
        }
    }
    // ---- qbk = Q[b].bk (per-warp redundant, overlapped) ----
    const float4* Q4 = reinterpret_cast<const float4*>(g_Q) + b * D4;
    const float4* bk4 = reinterpret_cast<const float4*>(bk);
    float qb = 0.f;
#pragma unroll
    for (int k = 0; k < 8; k++) {
        float4 a = Q4[k * 32 + lane], c = bk4[k * 32 + lane];
        qb += a.x * c.x + a.y * c.y + a.z * c.z + a.w * c.w;
    }
#pragma unroll
    for (int o = 16; o > 0; o >>= 1) qb += __shfl_xor_sync(0xffffffffu, qb, o);
    float curt = ct[b];

    float4 acc[8];
#pragma unroll
    for (int k = 0; k < 8; k++) acc[k] = make_float4(0.f, 0.f, 0.f, 0.f);
    float Ew = 0.f;

    // ---- mainloop ----
    for (int i = 0; i < nst; i++) {
        // temporal weight load hoisted off the dot-product critical chain
        int s = (st0 + i) * STAGE_ROWS + warp;
        float tsv = ts[b * S + s];

        if (issued < nst) cp_wait<DEPTH - 1>(); else cp_wait<0>();
        __syncthreads();

        const float4* bp = sbuf + ((size_t)(i % DEPTH) * STAGE_ROWS + warp) * D4;
        float4 v[8];
#pragma unroll
        for (int k = 0; k < 8; k++) v[k] = bp[k * 32 + lane];

        float tw = __expf(-0.01f * (curt - tsv));

        float d0 = 0.f, d1 = 0.f, d2 = 0.f, d3 = 0.f;
#pragma unroll
        for (int k = 0; k < 8; k++) {
            d0 += v[k].x * q[k].x; d1 += v[k].y * q[k].y;
            d2 += v[k].z * q[k].z; d3 += v[k].w * q[k].w;
        }
        float ds = (d0 + d1) + (d2 + d3);
#pragma unroll
        for (int o = 16; o > 0; o >>= 1) ds += __shfl_xor_sync(0xffffffffu, ds, o);

        float p = __expf((ds + qb) * 0.03125f * tw);
        if (lane == 0) g_p[b * S + s] = p;
        Ew += p;
#pragma unroll
        for (int k = 0; k < 8; k++) {
            acc[k].x += p * v[k].x; acc[k].y += p * v[k].y;
            acc[k].z += p * v[k].z; acc[k].w += p * v[k].w;
        }
        __syncthreads();

        if (issued < nst) {
            uint32_t dst = sb + (uint32_t)(issued % DEPTH) * STAGE_BYTES;
            const float* src = gsrc + (size_t)issued * STAGE_ROWS * D;
            for (int c = tid; c < STAGE_F4; c += 256)
                cp_async16(dst + (uint32_t)c * 16, src + (size_t)c * 4);
            cp_commit();
            issued++;
        }
    }

    // ---- epilogue: cross-warp reduce via (now free) sbuf ----
    float4* red = sbuf;
#pragma unroll
    for (int k = 0; k < 8; k++) red[(size_t)warp * D4 + k * 32 + lane] = acc[k];
    if (lane == 0) sE[warp] = Ew;
    __syncthreads();

    float4 r = red[tid];
#pragma unroll
    for (int w = 1; w < 8; w++) {
        float4 v = red[(size_t)w * D4 + tid];
        r.x += v.x; r.y += v.y; r.z += v.z; r.w += v.w;
    }
    reinterpret_cast<float4*>(g_macc)[(size_t)blockIdx.x * D4 + tid] = r;
    if (tid == 0) {
        float e = 0.f;
#pragma unroll
        for (int w = 0; w < 8; w++) e += sE[w];
        g_Epart[blockIdx.x] = e;
    }
}

// ============================================================
// k_combine: E = sum parts; attn = p/E; m = (sum macc)/E.  grid 16 x 256.
// ============================================================
__global__ void k_combine(float* __restrict__ attn)
{
    __shared__ float sInv;
    int b = blockIdx.x, tid = threadIdx.x;

    if (tid < 32) {
        float e = (tid < CTAS_PER_B) ? g_Epart[b * CTAS_PER_B + tid] : 0.f;
#pragma unroll
        for (int o = 16; o > 0; o >>= 1) e += __shfl_xor_sync(0xffffffffu, e, o);
        if (tid == 0) sInv = 1.f / e;
    }
    __syncthreads();
    float inv = sInv;

    for (int s = tid; s < S; s += 256) attn[b * S + s] = g_p[b * S + s] * inv;

    const float4* mp = reinterpret_cast<const float4*>(g_macc);
    float4 a = make_float4(0.f, 0.f, 0.f, 0.f);
#pragma unroll
    for (int c = 0; c < CTAS_PER_B; c++) {
        float4 v = mp[(size_t)(b * CTAS_PER_B + c) * D4 + tid];
        a.x += v.x; a.y += v.y; a.z += v.z; a.w += v.w;
    }
    a.x *= inv; a.y *= inv; a.z *= inv; a.w *= inv;
    reinterpret_cast<float4*>(g_m)[b * D4 + tid] = a;
}

// ============================================================
extern "C" void kernel_launch(void* const* d_in, const int* in_sizes, int n_in,
                              void* d_out, int out_size)
{
    const float* query = (const float*)d_in[0];
    const float* mb    = (const float*)d_in[1];
    const float* ts    = (const float*)d_in[2];
    const float* ct    = (const float*)d_in[3];
    const float* Wq    = (const float*)d_in[4];
    const float* bq    = (const float*)d_in[5];
    const float* Wk    = (const float*)d_in[6];
    const float* bk    = (const float*)d_in[7];
    const float* Wv    = (const float*)d_in[8];
    const float* bv    = (const float*)d_in[9];
    (void)in_sizes; (void)n_in; (void)out_size;

    float* attended = (float*)d_out;            // [16,1024]
    float* attn     = (float*)d_out + B * D;    // [16,4096]

    cudaFuncSetAttribute(k_main, cudaFuncAttributeMaxDynamicSharedMemorySize,
                         SMEM_MAIN);

    k_gemm_nt<<<128, 256>>>(query, Wq, bq, nullptr, 0);        // g_Q
    k_qt<<<dim3(8, QT_SPLITS), 128>>>(Wk);                     // qt partials
    k_main<<<NCTA_MAIN, 256, SMEM_MAIN>>>(mb, ts, ct, bk);     // 268 MB pass
    k_combine<<<B, 256>>>(attn);                               // E, attn, g_m
    k_gemm_nt<<<128, 256>>>(nullptr, Wv, bv, attended, 1);     // attended
}

// round 4
// speedup vs baseline: 1.0938x; 1.0708x over previous
#include <cuda_runtime.h>
#include <cstdint>

// CausalMemoryAttention: B=16, S=4096, D=1024
// Exact restructure (validated, rel_err 1.3e-6):
//   Q  = query @ Wq^T + bq ; qt = Q @ Wk ; qbk = Q.bk
//   score[b,s] = (mb[b,s].qt[b] + qbk[b]) / 32 * tw[b,s],  tw = exp(-0.01*(ct-ts))
//   p = exp(score); attn = p/sum p; m = (sum p*mb)/sum p; attended = m@Wv^T + bv
// memory_bank (268 MB) is streamed exactly once via a cp.async smem pipeline.

#define B 16
#define S 4096
#define D 1024
#define D4 256
#define QT_SPLITS 16
#define CTAS_PER_B 18
#define NCTA_MAIN (B * CTAS_PER_B)        // 288 (single wave at 2 CTA/SM)
#define DEPTH 3
#define STAGE_ROWS 8
#define STAGE_F4 (STAGE_ROWS * D4)        // 2048 float4
#define STAGE_BYTES (STAGE_F4 * 16)       // 32 KB
#define SMEM_MAIN (DEPTH * STAGE_BYTES)   // 96 KB

// -------- scratch (device globals; no dynamic allocation) --------
__device__ __align__(16) float g_Q[B * D];
__device__ __align__(16) float g_qt_part[QT_SPLITS * B * D];
__device__ __align__(16) float g_tw[B * S];
__device__ __align__(16) float g_p[B * S];
__device__ __align__(16) float g_macc[NCTA_MAIN * D];
__device__ float g_Epart[NCTA_MAIN];
__device__ __align__(16) float g_m[B * D];

// ---------------- cp.async helpers ----------------
__device__ __forceinline__ void cp_async16(uint32_t smem, const void* gmem) {
    asm volatile("cp.async.cg.shared.global [%0], [%1], 16;" :: "r"(smem), "l"(gmem));
}
__device__ __forceinline__ void cp_commit() {
    asm volatile("cp.async.commit_group;" ::: "memory");
}
template <int N> __device__ __forceinline__ void cp_wait() {
    asm volatile("cp.async.wait_group %0;" :: "n"(N) : "memory");
}

// ============================================================
// k_gemm_nt: Out[b,d] = sum_e X[b,e] * W[d,e] + bias[d]
// mode 0: X=query -> g_Q ; mode 1: X=g_m -> OutExt (attended)
// ============================================================
__global__ __launch_bounds__(256) void k_gemm_nt(
    const float* __restrict__ Xext, const float* __restrict__ W,
    const float* __restrict__ bias, float* __restrict__ OutExt, int mode)
{
    int warp = threadIdx.x >> 5, lane = threadIdx.x & 31;
    int d = blockIdx.x * 8 + warp;

    const float* Xp = (mode == 0) ? Xext : g_m;
    float* Outp = (mode == 0) ? g_Q : OutExt;

    const float4* W4 = reinterpret_cast<const float4*>(W) + (size_t)d * D4;
    const float4* X4 = reinterpret_cast<const float4*>(Xp);

    float4 w[8];
#pragma unroll
    for (int k = 0; k < 8; k++) w[k] = W4[k * 32 + lane];
    float bb = bias[d];

#pragma unroll
    for (int b = 0; b < B; b += 2) {
        float sa = 0.f, sb = 0.f;
#pragma unroll
        for (int k = 0; k < 8; k++) {
            float4 xa = X4[b * D4 + k * 32 + lane];
            float4 xb = X4[(b + 1) * D4 + k * 32 + lane];
            sa += xa.x * w[k].x; sa += xa.y * w[k].y;
            sa += xa.z * w[k].z; sa += xa.w * w[k].w;
            sb += xb.x * w[k].x; sb += xb.y * w[k].y;
            sb += xb.z * w[k].z; sb += xb.w * w[k].w;
        }
#pragma unroll
        for (int o = 16; o > 0; o >>= 1) {
            sa += __shfl_xor_sync(0xffffffffu, sa, o);
            sb += __shfl_xor_sync(0xffffffffu, sb, o);
        }
        if (lane == 0) {
            Outp[b * D + d] = sa + bb;
            Outp[(b + 1) * D + d] = sb + bb;
        }
    }
}

// ============================================================
// k_qt: partial qt[b,e] = sum_{d in split} Q[b,d] * Wk[d,e]
// grid (8 e-tiles of 128, 16 d-splits of 64), 128 threads.
// ============================================================
__global__ __launch_bounds__(128) void k_qt(const float* __restrict__ Wk)
{
    __shared__ __align__(16) float Qs[64 * 16];
    int e = blockIdx.x * 128 + threadIdx.x;
    int d0 = blockIdx.y * 64;

    for (int i = threadIdx.x; i < 1024; i += 128) {
        int bb = i >> 6, dl = i & 63;
        Qs[dl * 16 + bb] = g_Q[bb * D + d0 + dl];
    }
    __syncthreads();

    float acc[16];
#pragma unroll
    for (int bb = 0; bb < 16; bb++) acc[bb] = 0.f;

#pragma unroll 8
    for (int dl = 0; dl < 64; dl++) {
        float w = Wk[(size_t)(d0 + dl) * D + e];
        const float4* q4 = reinterpret_cast<const float4*>(&Qs[dl * 16]);
#pragma unroll
        for (int j = 0; j < 4; j++) {
            float4 q = q4[j];
            acc[4 * j + 0] += q.x * w;
            acc[4 * j + 1] += q.y * w;
            acc[4 * j + 2] += q.z * w;
            acc[4 * j + 3] += q.w * w;
        }
    }
#pragma unroll
    for (int bb = 0; bb < 16; bb++)
        g_qt_part[(size_t)(blockIdx.y * 16 + bb) * D + e] = acc[bb];
}

// ============================================================
// k_tw: temporal weights tw[b,s] = exp(-0.01*(ct[b]-ts[b,s])).
// grid 64 x 256, float4. Each block stays within one batch b.
// (Also shifts k_main to launch index 3 so ncu captures it.)
// ============================================================
__global__ void k_tw(const float* __restrict__ ts, const float* __restrict__ ct)
{
    int idx = blockIdx.x * 1024 + threadIdx.x * 4;
    int b = idx >> 12;
    float curt = ct[b];
    float4 t = *reinterpret_cast<const float4*>(ts + idx);
    float4 w;
    w.x = __expf(-0.01f * (curt - t.x));
    w.y = __expf(-0.01f * (curt - t.y));
    w.z = __expf(-0.01f * (curt - t.z));
    w.w = __expf(-0.01f * (curt - t.w));
    *reinterpret_cast<float4*>(g_tw + idx) = w;
}

// ============================================================
// k_main: single streaming pass over memory_bank via cp.async pipeline.
// CTA = (b, 1/18th of the 512 8-row stages). Warp w computes row w of
// each stage. Refill of the consumed slot is issued BEFORE the compute
// chain (sync right after register v-loads frees the slot).
// Prologue overlaps the qt split-reduce + qbk with the DRAM ramp.
// ============================================================
__global__ __launch_bounds__(256, 2) void k_main(
    const float* __restrict__ mb, const float* __restrict__ bk)
{
    extern __shared__ __align__(16) float4 sbuf[];   // DEPTH * STAGE_F4
    __shared__ float sE[8];

    int b = blockIdx.x / CTAS_PER_B;
    int j = blockIdx.x % CTAS_PER_B;
    int warp = threadIdx.x >> 5, lane = threadIdx.x & 31, tid = threadIdx.x;

    // 512 stages per batch split 8x29 + 10x28
    int nst = (j < 8) ? 29 : 28;
    int st0 = (j < 8) ? j * 29 : 232 + (j - 8) * 28;

    const float* gsrc = mb + (size_t)b * S * D + (size_t)st0 * STAGE_ROWS * D;
    uint32_t sb = (uint32_t)__cvta_generic_to_shared(sbuf);

    // ---- prologue: issue first DEPTH stages ----
    int issued = 0;
    for (; issued < DEPTH && issued < nst; issued++) {
        uint32_t dst = sb + (uint32_t)(issued % DEPTH) * STAGE_BYTES;
        const float* src = gsrc + (size_t)issued * STAGE_ROWS * D;
        for (int c = tid; c < STAGE_F4; c += 256)
            cp_async16(dst + (uint32_t)c * 16, src + (size_t)c * 4);
        cp_commit();
    }

    // ---- qt split-reduce for this b (overlaps DRAM ramp) ----
    float4 q[8];
#pragma unroll
    for (int k = 0; k < 8; k++) q[k] = make_float4(0.f, 0.f, 0.f, 0.f);
    for (int sp = 0; sp < QT_SPLITS; sp++) {
        const float4* qp = reinterpret_cast<const float4*>(g_qt_part)
                           + (size_t)(sp * B + b) * D4;
#pragma unroll
        for (int k = 0; k < 8; k++) {
            float4 v = qp[k * 32 + lane];
            q[k].x += v.x; q[k].y += v.y; q[k].z += v.z; q[k].w += v.w;
        }
    }
    // ---- qbk = Q[b].bk (per-warp redundant, overlapped) ----
    const float4* Q4 = reinterpret_cast<const float4*>(g_Q) + b * D4;
    const float4* bk4 = reinterpret_cast<const float4*>(bk);
    float qb = 0.f;
#pragma unroll
    for (int k = 0; k < 8; k++) {
        float4 a = Q4[k * 32 + lane], c = bk4[k * 32 + lane];
        qb += a.x * c.x + a.y * c.y + a.z * c.z + a.w * c.w;
    }
#pragma unroll
    for (int o = 16; o > 0; o >>= 1) qb += __shfl_xor_sync(0xffffffffu, qb, o);

    float4 acc[8];
#pragma unroll
    for (int k = 0; k < 8; k++) acc[k] = make_float4(0.f, 0.f, 0.f, 0.f);
    float Ew = 0.f;

    // ---- mainloop ----
    for (int i = 0; i < nst; i++) {
        int s = (st0 + i) * STAGE_ROWS + warp;
        float twv = g_tw[b * S + s];     // L2-hot prefetch, off the chain

        if (issued < nst) cp_wait<DEPTH - 1>(); else cp_wait<0>();
        __syncthreads();

        const float4* bp = sbuf + ((size_t)(i % DEPTH) * STAGE_ROWS + warp) * D4;
        float4 v[8];
#pragma unroll
        for (int k = 0; k < 8; k++) v[k] = bp[k * 32 + lane];
        __syncthreads();                 // slot consumed -> free for refill

        // refill the freed slot BEFORE the long compute chain
        if (issued < nst) {
            uint32_t dst = sb + (uint32_t)(issued % DEPTH) * STAGE_BYTES;
            const float* src = gsrc + (size_t)issued * STAGE_ROWS * D;
            for (int c = tid; c < STAGE_F4; c += 256)
                cp_async16(dst + (uint32_t)c * 16, src + (size_t)c * 4);
            cp_commit();
            issued++;
        }

        float d0 = 0.f, d1 = 0.f, d2 = 0.f, d3 = 0.f;
#pragma unroll
        for (int k = 0; k < 8; k++) {
            d0 += v[k].x * q[k].x; d1 += v[k].y * q[k].y;
            d2 += v[k].z * q[k].z; d3 += v[k].w * q[k].w;
        }
        float ds = (d0 + d1) + (d2 + d3);
#pragma unroll
        for (int o = 16; o > 0; o >>= 1) ds += __shfl_xor_sync(0xffffffffu, ds, o);

        float p = __expf((ds + qb) * 0.03125f * twv);
        if (lane == 0) g_p[b * S + s] = p;
        Ew += p;
#pragma unroll
        for (int k = 0; k < 8; k++) {
            acc[k].x += p * v[k].x; acc[k].y += p * v[k].y;
            acc[k].z += p * v[k].z; acc[k].w += p * v[k].w;
        }
    }

    // ---- epilogue: cross-warp reduce via sbuf (wait for last refill reads) ----
    cp_wait<0>();
    __syncthreads();
    float4* red = sbuf;
#pragma unroll
    for (int k = 0; k < 8; k++) red[(size_t)warp * D4 + k * 32 + lane] = acc[k];
    if (lane == 0) sE[warp] = Ew;
    __syncthreads();

    float4 r = red[tid];
#pragma unroll
    for (int w = 1; w < 8; w++) {
        float4 v = red[(size_t)w * D4 + tid];
        r.x += v.x; r.y += v.y; r.z += v.z; r.w += v.w;
    }
    reinterpret_cast<float4*>(g_macc)[(size_t)blockIdx.x * D4 + tid] = r;
    if (tid == 0) {
        float e = 0.f;
#pragma unroll
        for (int w = 0; w < 8; w++) e += sE[w];
        g_Epart[blockIdx.x] = e;
    }
}

// ============================================================
// k_combine: widened to 80 blocks. block = (role, b):
//   role 0   : m[b] = (sum_c macc[b,c]) / E
//   role 1..4: attn[b, (role-1)*1024 .. ] = p * (1/E)
// Every block redundantly computes E from the 18 partials (deterministic).
// ============================================================
__global__ __launch_bounds__(256) void k_combine(float* __restrict__ attn)
{
    __shared__ float sInv;
    int b = blockIdx.x & 15;
    int role = blockIdx.x >> 4;        // 0..4
    int tid = threadIdx.x, lane = tid & 31;

    if (tid < 32) {
        float e = (lane < CTAS_PER_B) ? g_Epart[b * CTAS_PER_B + lane] : 0.f;
#pragma unroll
        for (int o = 16; o > 0; o >>= 1) e += __shfl_xor_sync(0xffffffffu, e, o);
        if (lane == 0) sInv = 1.f / e;
    }
    __syncthreads();
    float inv = sInv;

    if (role == 0) {
        const float4* mp = reinterpret_cast<const float4*>(g_macc);
        float4 a = make_float4(0.f, 0.f, 0.f, 0.f);
#pragma unroll
        for (int c = 0; c < CTAS_PER_B; c++) {
            float4 v = mp[(size_t)(b * CTAS_PER_B + c) * D4 + tid];
            a.x += v.x; a.y += v.y; a.z += v.z; a.w += v.w;
        }
        a.x *= inv; a.y *= inv; a.z *= inv; a.w *= inv;
        reinterpret_cast<float4*>(g_m)[b * D4 + tid] = a;
    } else {
        int s = (role - 1) * 1024 + tid * 4;
        float4 p = *reinterpret_cast<const float4*>(g_p + b * S + s);
        p.x *= inv; p.y *= inv; p.z *= inv; p.w *= inv;
        *reinterpret_cast<float4*>(attn + b * S + s) = p;
    }
}

// ============================================================
extern "C" void kernel_launch(void* const* d_in, const int* in_sizes, int n_in,
                              void* d_out, int out_size)
{
    const float* query = (const float*)d_in[0];
    const float* mb    = (const float*)d_in[1];
    const float* ts    = (const float*)d_in[2];
    const float* ct    = (const float*)d_in[3];
    const float* Wq    = (const float*)d_in[4];
    const float* bq    = (const float*)d_in[5];
    const float* Wk    = (const float*)d_in[6];
    const float* bk    = (const float*)d_in[7];
    const float* Wv    = (const float*)d_in[8];
    const float* bv    = (const float*)d_in[9];
    (void)in_sizes; (void)n_in; (void)out_size;

    float* attended = (float*)d_out;            // [16,1024]
    float* attn     = (float*)d_out + B * D;    // [16,4096]

    cudaFuncSetAttribute(k_main, cudaFuncAttributeMaxDynamicSharedMemorySize,
                         SMEM_MAIN);

    k_gemm_nt<<<128, 256>>>(query, Wq, bq, nullptr, 0);        // 0: g_Q
    k_qt<<<dim3(8, QT_SPLITS), 128>>>(Wk);                     // 1: qt partials
    k_tw<<<64, 256>>>(ts, ct);                                 // 2: g_tw
    k_main<<<NCTA_MAIN, 256, SMEM_MAIN>>>(mb, bk);             // 3: 268 MB pass
    k_combine<<<80, 256>>>(attn);                              // 4: E, attn, g_m
    k_gemm_nt<<<128, 256>>>(nullptr, Wv, bv, attended, 1);     // 5: attended
}